// round 15
// baseline (speedup 1.0000x reference)
#include <cuda_runtime.h>
#include <cuda_fp16.h>
#include <math.h>
#include <stdint.h>

#define NN 1024
#define HH 64

__device__ float    g_A[NN * HH];     // z_c @ W1[:64]  (fp32)
__device__ float    g_B[NN * HH];     // z_d @ W1[64:] + b1 (fp32)
__device__ uint32_t g_Bh[NN * 32];    // half2-packed B
__device__ float    g_T1[NN * NN];
__device__ double   g_acc;
__device__ int      g_cnt;

// ---------------------------------------------------------------------------
#define MMA16816(c, a0, a1, a2, a3, b0, b1)                                   \
    asm("mma.sync.aligned.m16n8k16.row.col.f32.f16.f16.f32 "                  \
        "{%0,%1,%2,%3}, {%4,%5,%6,%7}, {%8,%9}, {%0,%1,%2,%3};"               \
        : "+f"((c)[0]), "+f"((c)[1]), "+f"((c)[2]), "+f"((c)[3])              \
        : "r"(a0), "r"(a1), "r"(a2), "r"(a3), "r"(b0), "r"(b1))

__device__ __forceinline__ uint32_t pack_h2(float e0, float e1) {  // lo=e0, hi=e1
    uint32_t r;
    asm("cvt.rn.f16x2.f32 %0, %1, %2;" : "=r"(r) : "f"(e1), "f"(e0));
    return r;
}
// relu(a + b) in packed fp16
__device__ __forceinline__ uint32_t frag_h2(uint32_t a, uint32_t b) {
    __half2 r = __hmax2(__hadd2(*(__half2*)&a, *(__half2*)&b),
                        __half2half2(__ushort_as_half(0)));
    return *(uint32_t*)&r;
}

// ---------------------------------------------------------------------------
// Kernel 1: precompute A (fp32) and B (fp32 + half2-packed copy).
// ---------------------------------------------------------------------------
__global__ void prep_kernel(const float* __restrict__ zc,
                            const float* __restrict__ zd,
                            const float* __restrict__ W1,
                            const float* __restrict__ b1) {
    int which = blockIdx.y;
    if (blockIdx.x == 0 && which == 0 && threadIdx.x == 0) {
        g_acc = 0.0;
        g_cnt = 0;
    }
    int row = blockIdx.x * 4 + (threadIdx.x >> 6);
    int col = threadIdx.x & 63;
    const float* src = which ? zd : zc;
    const float* w   = W1 + (which ? 64 * HH : 0);
    float s0 = which ? b1[col] : 0.0f, s1 = 0.f, s2 = 0.f, s3 = 0.f;
#pragma unroll
    for (int k = 0; k < 64; k += 4) {
        s0 = fmaf(src[row * 64 + k],     w[(k) * HH + col],     s0);
        s1 = fmaf(src[row * 64 + k + 1], w[(k + 1) * HH + col], s1);
        s2 = fmaf(src[row * 64 + k + 2], w[(k + 2) * HH + col], s2);
        s3 = fmaf(src[row * 64 + k + 3], w[(k + 3) * HH + col], s3);
    }
    float s = (s0 + s1) + (s2 + s3);
    if (which) {
        g_B[row * HH + col] = s;
        float s_hi = __shfl_down_sync(0xffffffffu, s, 1);
        if ((col & 1) == 0)
            g_Bh[row * 32 + (col >> 1)] = pack_h2(s, s_hi);
    } else {
        g_A[row * HH + col] = s;
    }
}

// ---------------------------------------------------------------------------
// Kernel 2: pairwise MLP via HMMA (fp16 x fp16, fp32 acc).
// R15: occupancy 4 (16 warps/SM) — epilogue constants moved to a lane-indexed
//      smem table to fit the 128-reg cap; Bf stays in registers; fp16 frag
//      build (4 LDS + 4 HADD2 + 4 HMAX2 per k-step); Bi software-pipelined.
// ---------------------------------------------------------------------------
#define JSTRIDE 37   // grid = 16 * 37 = 592 CTAs = 4/SM, one wave at occ 4

__global__ __launch_bounds__(128, 4) void pair_mma_kernel(
    const float* __restrict__ W2, const float* __restrict__ b2,
    const float* __restrict__ Wo, const float* __restrict__ bo_p) {
    __shared__ uint32_t sA2[32 * 72];   // [k2][m] half2(A[m][2k2],A[m][2k2+1])
    __shared__ uint4    sEp[8 * 32];    // [nt*32+lane]: b2[n],b2[n+1],Wo[n],Wo[n+1]

    const int tid  = threadIdx.x;
    const int lane = tid & 31;
    const int wid  = tid >> 5;
    const int gid  = lane >> 2;      // 0..7
    const int tid4 = lane & 3;       // 0..3

    const int jb  = blockIdx.x / JSTRIDE;    // 0..15
    const int s0i = blockIdx.x % JSTRIDE;    // starting i
    const int j0  = jb * 64;

    // ---- stage A block as packed half2, transposed ----
    for (int idx = tid; idx < 2048; idx += 128) {
        int m = idx >> 5, k2 = idx & 31;
        float2 f = *(const float2*)(g_A + (size_t)(j0 + m) * 64 + 2 * k2);
        sA2[k2 * 72 + m] = pack_h2(f.x, f.y);
    }

    // ---- epilogue-constant table (warp 0; lane-indexed, conflict-free) ----
    if (wid == 0) {
#pragma unroll
        for (int nt = 0; nt < 8; ++nt) {
            int n = 8 * nt + 2 * (lane & 3);
            uint4 e;
            e.x = __float_as_uint(b2[n]);
            e.y = __float_as_uint(b2[n + 1]);
            e.z = __float_as_uint(Wo[n]);
            e.w = __float_as_uint(Wo[n + 1]);
            sEp[nt * 32 + lane] = e;
        }
    }

    // ---- preload W2 fragments (fp16) into registers ----
    uint32_t Bf[4][8][2];
#pragma unroll
    for (int ks = 0; ks < 4; ++ks) {
#pragma unroll
        for (int nt = 0; nt < 8; ++nt) {
            int k0 = 16 * ks + 2 * tid4;
            int n  = 8 * nt + gid;
            Bf[ks][nt][0] = pack_h2(W2[(k0 + 0) * HH + n], W2[(k0 + 1) * HH + n]);
            Bf[ks][nt][1] = pack_h2(W2[(k0 + 8) * HH + n], W2[(k0 + 9) * HH + n]);
        }
    }

    const float bo = bo_p[0];
    const int m0 = wid * 16 + gid;   // this thread's first row in j-block

    __syncthreads();                 // sA2 + sEp ready (only barrier)

    // ---- prime the Bi pipeline ----
    uint32_t nbi[8];
    {
        const uint32_t* Bi = g_Bh + (size_t)s0i * 32;
#pragma unroll
        for (int ks = 0; ks < 4; ++ks) {
            nbi[2 * ks]     = Bi[8 * ks + tid4];
            nbi[2 * ks + 1] = Bi[8 * ks + 4 + tid4];
        }
    }

    for (int i = s0i; i < NN; i += JSTRIDE) {
        uint32_t bi[8];
#pragma unroll
        for (int q = 0; q < 8; ++q) bi[q] = nbi[q];

        if (i + JSTRIDE < NN) {
            const uint32_t* Bn = g_Bh + (size_t)(i + JSTRIDE) * 32;
#pragma unroll
            for (int ks = 0; ks < 4; ++ks) {
                nbi[2 * ks]     = Bn[8 * ks + tid4];
                nbi[2 * ks + 1] = Bn[8 * ks + 4 + tid4];
            }
        }

        float acc[8][4];
#pragma unroll
        for (int nt = 0; nt < 8; ++nt)
#pragma unroll
            for (int q = 0; q < 4; ++q) acc[nt][q] = 0.0f;

#pragma unroll
        for (int ks = 0; ks < 4; ++ks) {
            const int k2 = 8 * ks + tid4;
            uint32_t a0 = frag_h2(sA2[k2 * 72 + m0],           bi[2 * ks]);
            uint32_t a1 = frag_h2(sA2[k2 * 72 + m0 + 8],       bi[2 * ks]);
            uint32_t a2 = frag_h2(sA2[(k2 + 4) * 72 + m0],     bi[2 * ks + 1]);
            uint32_t a3 = frag_h2(sA2[(k2 + 4) * 72 + m0 + 8], bi[2 * ks + 1]);

#pragma unroll
            for (int nt = 0; nt < 8; ++nt)
                MMA16816(acc[nt], a0, a1, a2, a3,
                         Bf[ks][nt][0], Bf[ks][nt][1]);
        }

        // epilogue: constants from smem table; rows m0 and m0+8
        float sA0 = 0.f, sA1 = 0.f;
#pragma unroll
        for (int nt = 0; nt < 8; ++nt) {
            uint4 e = sEp[nt * 32 + lane];
            float b2x = __uint_as_float(e.x), b2y = __uint_as_float(e.y);
            float wox = __uint_as_float(e.z), woy = __uint_as_float(e.w);
            sA0 = fmaf(fmaxf(acc[nt][0] + b2x, 0.f), wox, sA0);
            sA0 = fmaf(fmaxf(acc[nt][1] + b2y, 0.f), woy, sA0);
            sA1 = fmaf(fmaxf(acc[nt][2] + b2x, 0.f), wox, sA1);
            sA1 = fmaf(fmaxf(acc[nt][3] + b2y, 0.f), woy, sA1);
        }
        sA0 += __shfl_xor_sync(0xffffffffu, sA0, 1);
        sA0 += __shfl_xor_sync(0xffffffffu, sA0, 2);
        sA1 += __shfl_xor_sync(0xffffffffu, sA1, 1);
        sA1 += __shfl_xor_sync(0xffffffffu, sA1, 2);
        if (tid4 == 0) {
            g_T1[(size_t)i * NN + j0 + m0]     = sA0 + bo;
            g_T1[(size_t)i * NN + j0 + m0 + 8] = sA1 + bo;
        }
    }
}

// ---------------------------------------------------------------------------
// Kernel 3: logsumexp + diagonal + fused final reduction.
// ---------------------------------------------------------------------------
__global__ void lse_kernel(float* out) {
    __shared__ float sm[8], ss[8];
    const int tid = threadIdx.x;
    const int lane = tid & 31, wid = tid >> 5;
    double local = 0.0;

#pragma unroll 1
    for (int r = 0; r < 8; ++r) {
        const int i = blockIdx.x * 8 + r;
        const float4 v = ((const float4*)(g_T1 + (size_t)i * NN))[tid];

        float m = fmaxf(fmaxf(v.x, v.y), fmaxf(v.z, v.w));
#pragma unroll
        for (int o = 16; o > 0; o >>= 1)
            m = fmaxf(m, __shfl_xor_sync(0xffffffffu, m, o));
        if (lane == 0) sm[wid] = m;
        __syncthreads();
        float bm = sm[0];
#pragma unroll
        for (int w = 1; w < 8; ++w) bm = fmaxf(bm, sm[w]);

        float s = __expf(v.x - bm) + __expf(v.y - bm) +
                  __expf(v.z - bm) + __expf(v.w - bm);
#pragma unroll
        for (int o = 16; o > 0; o >>= 1)
            s += __shfl_xor_sync(0xffffffffu, s, o);
        if (lane == 0) ss[wid] = s;
        __syncthreads();

        if (tid == 0) {
            float tot = ss[0] + ss[1] + ss[2] + ss[3] +
                        ss[4] + ss[5] + ss[6] + ss[7];
            local += (double)g_T1[(size_t)i * NN + i]
                   - ((double)bm + log((double)tot));
        }
        __syncthreads();
    }

    if (tid == 0) {
        atomicAdd(&g_acc, local);
        __threadfence();
        if (atomicAdd(&g_cnt, 1) == 127) {
            double acc = atomicAdd(&g_acc, 0.0);
            out[0] = (float)(acc / NN + log((double)NN));
        }
    }
}

// ---------------------------------------------------------------------------
extern "C" void kernel_launch(void* const* d_in, const int* in_sizes, int n_in,
                              void* d_out, int out_size) {
    const float* z_c = (const float*)d_in[0];
    const float* z_d = (const float*)d_in[1];
    const float* W1  = (const float*)d_in[2];
    const float* b1  = (const float*)d_in[3];
    const float* W2  = (const float*)d_in[4];
    const float* b2  = (const float*)d_in[5];
    const float* Wo  = (const float*)d_in[6];
    const float* bo  = (const float*)d_in[7];
    float* out = (float*)d_out;

    prep_kernel<<<dim3(NN / 4, 2), 256>>>(z_c, z_d, W1, b1);
    pair_mma_kernel<<<16 * JSTRIDE, 128>>>(W2, b2, Wo, bo);
    lse_kernel<<<128, 256>>>(out);
}

// round 16
// speedup vs baseline: 1.1753x; 1.1753x over previous
#include <cuda_runtime.h>
#include <cuda_fp16.h>
#include <math.h>
#include <stdint.h>

#define NN 1024
#define HH 64

__device__ float    g_A[NN * HH];     // z_c @ W1[:64]  (fp32)
__device__ float    g_B[NN * HH];     // z_d @ W1[64:] + b1 (fp32)
__device__ uint32_t g_Bh[NN * 32];    // half2-packed B
__device__ float    g_T1[NN * NN];
__device__ double   g_acc;
__device__ int      g_cnt;

// ---------------------------------------------------------------------------
// fp16-accumulate MMA: C/D are 2 regs (half2 x2): {(c0,c1),(c2,c3)}
#define MMA16816H(c, a0, a1, a2, a3, b0, b1)                                  \
    asm("mma.sync.aligned.m16n8k16.row.col.f16.f16.f16.f16 "                  \
        "{%0,%1}, {%2,%3,%4,%5}, {%6,%7}, {%0,%1};"                           \
        : "+r"((c)[0]), "+r"((c)[1])                                          \
        : "r"(a0), "r"(a1), "r"(a2), "r"(a3), "r"(b0), "r"(b1))

__device__ __forceinline__ uint32_t pack_h2(float e0, float e1) {  // lo=e0, hi=e1
    uint32_t r;
    asm("cvt.rn.f16x2.f32 %0, %1, %2;" : "=r"(r) : "f"(e1), "f"(e0));
    return r;
}
// relu(a + b) in packed fp16
__device__ __forceinline__ uint32_t frag_h2(uint32_t a, uint32_t b) {
    __half2 r = __hmax2(__hadd2(*(__half2*)&a, *(__half2*)&b),
                        __half2half2(__ushort_as_half(0)));
    return *(uint32_t*)&r;
}

// ---------------------------------------------------------------------------
// Kernel 1: precompute A (fp32) and B (fp32 + half2-packed copy).
// ---------------------------------------------------------------------------
__global__ void prep_kernel(const float* __restrict__ zc,
                            const float* __restrict__ zd,
                            const float* __restrict__ W1,
                            const float* __restrict__ b1) {
    int which = blockIdx.y;
    if (blockIdx.x == 0 && which == 0 && threadIdx.x == 0) {
        g_acc = 0.0;
        g_cnt = 0;
    }
    int row = blockIdx.x * 4 + (threadIdx.x >> 6);
    int col = threadIdx.x & 63;
    const float* src = which ? zd : zc;
    const float* w   = W1 + (which ? 64 * HH : 0);
    float s0 = which ? b1[col] : 0.0f, s1 = 0.f, s2 = 0.f, s3 = 0.f;
#pragma unroll
    for (int k = 0; k < 64; k += 4) {
        s0 = fmaf(src[row * 64 + k],     w[(k) * HH + col],     s0);
        s1 = fmaf(src[row * 64 + k + 1], w[(k + 1) * HH + col], s1);
        s2 = fmaf(src[row * 64 + k + 2], w[(k + 2) * HH + col], s2);
        s3 = fmaf(src[row * 64 + k + 3], w[(k + 3) * HH + col], s3);
    }
    float s = (s0 + s1) + (s2 + s3);
    if (which) {
        g_B[row * HH + col] = s;
        float s_hi = __shfl_down_sync(0xffffffffu, s, 1);
        if ((col & 1) == 0)
            g_Bh[row * 32 + (col >> 1)] = pack_h2(s, s_hi);
    } else {
        g_A[row * HH + col] = s;
    }
}

// ---------------------------------------------------------------------------
// Kernel 2: pairwise MLP via HMMA, fp16 x fp16 with fp16 ACCUMULATE
// (2x tensor rate if f32-acc is half-rate). Two accumulator groups
// (ks 0-1 / ks 2-3) summed in fp32 at epilogue to halve fp16 accum error.
// occ 3, Bf + epilogue consts in regs, fp16 frag build, Bi pipelined.
// ---------------------------------------------------------------------------
#define JSTRIDE 27   // CTAs per j-block; grid = 16 * 27 = 432 (1 wave at occ 3)

__global__ __launch_bounds__(128, 3) void pair_mma_kernel(
    const float* __restrict__ W2, const float* __restrict__ b2,
    const float* __restrict__ Wo, const float* __restrict__ bo_p) {
    __shared__ uint32_t sA2[32 * 72];   // [k2][m] half2(A[m][2k2],A[m][2k2+1])

    const int tid  = threadIdx.x;
    const int lane = tid & 31;
    const int wid  = tid >> 5;
    const int gid  = lane >> 2;      // 0..7
    const int tid4 = lane & 3;       // 0..3

    const int jb  = blockIdx.x / JSTRIDE;    // 0..15
    const int s0i = blockIdx.x % JSTRIDE;    // starting i
    const int j0  = jb * 64;

    // ---- stage A block as packed half2, transposed ----
    for (int idx = tid; idx < 2048; idx += 128) {
        int m = idx >> 5, k2 = idx & 31;
        float2 f = *(const float2*)(g_A + (size_t)(j0 + m) * 64 + 2 * k2);
        sA2[k2 * 72 + m] = pack_h2(f.x, f.y);
    }

    // ---- preload W2 fragments (fp16) into registers ----
    uint32_t Bf[4][8][2];
#pragma unroll
    for (int ks = 0; ks < 4; ++ks) {
#pragma unroll
        for (int nt = 0; nt < 8; ++nt) {
            int k0 = 16 * ks + 2 * tid4;
            int n  = 8 * nt + gid;
            Bf[ks][nt][0] = pack_h2(W2[(k0 + 0) * HH + n], W2[(k0 + 1) * HH + n]);
            Bf[ks][nt][1] = pack_h2(W2[(k0 + 8) * HH + n], W2[(k0 + 9) * HH + n]);
        }
    }

    // ---- per-thread epilogue constants ----
    float2 b2r[8], wor[8];
#pragma unroll
    for (int nt = 0; nt < 8; ++nt) {
        int n = 8 * nt + 2 * tid4;
        b2r[nt] = make_float2(b2[n], b2[n + 1]);
        wor[nt] = make_float2(Wo[n], Wo[n + 1]);
    }
    const float bo = bo_p[0];

    const int m0 = wid * 16 + gid;   // this thread's first row in j-block

    __syncthreads();                 // sA2 ready (only barrier in kernel)

    // ---- prime the Bi pipeline ----
    uint32_t nbi[8];
    {
        const uint32_t* Bi = g_Bh + (size_t)s0i * 32;
#pragma unroll
        for (int ks = 0; ks < 4; ++ks) {
            nbi[2 * ks]     = Bi[8 * ks + tid4];
            nbi[2 * ks + 1] = Bi[8 * ks + 4 + tid4];
        }
    }

    for (int i = s0i; i < NN; i += JSTRIDE) {
        uint32_t bi[8];
#pragma unroll
        for (int q = 0; q < 8; ++q) bi[q] = nbi[q];

        if (i + JSTRIDE < NN) {
            const uint32_t* Bn = g_Bh + (size_t)(i + JSTRIDE) * 32;
#pragma unroll
            for (int ks = 0; ks < 4; ++ks) {
                nbi[2 * ks]     = Bn[8 * ks + tid4];
                nbi[2 * ks + 1] = Bn[8 * ks + 4 + tid4];
            }
        }

        // two fp16 accumulator groups (halve accumulation rounding)
        uint32_t accP[8][2], accQ[8][2];
#pragma unroll
        for (int nt = 0; nt < 8; ++nt) {
            accP[nt][0] = 0u; accP[nt][1] = 0u;
            accQ[nt][0] = 0u; accQ[nt][1] = 0u;
        }

#pragma unroll
        for (int ks = 0; ks < 4; ++ks) {
            const int k2 = 8 * ks + tid4;
            uint32_t a0 = frag_h2(sA2[k2 * 72 + m0],           bi[2 * ks]);
            uint32_t a1 = frag_h2(sA2[k2 * 72 + m0 + 8],       bi[2 * ks]);
            uint32_t a2 = frag_h2(sA2[(k2 + 4) * 72 + m0],     bi[2 * ks + 1]);
            uint32_t a3 = frag_h2(sA2[(k2 + 4) * 72 + m0 + 8], bi[2 * ks + 1]);

            if (ks < 2) {
#pragma unroll
                for (int nt = 0; nt < 8; ++nt)
                    MMA16816H(accP[nt], a0, a1, a2, a3,
                              Bf[ks][nt][0], Bf[ks][nt][1]);
            } else {
#pragma unroll
                for (int nt = 0; nt < 8; ++nt)
                    MMA16816H(accQ[nt], a0, a1, a2, a3,
                              Bf[ks][nt][0], Bf[ks][nt][1]);
            }
        }

        // epilogue: D = fp32(accP) + fp32(accQ) + b2; relu; dot Wo
        float sA0 = 0.f, sA1 = 0.f;
#pragma unroll
        for (int nt = 0; nt < 8; ++nt) {
            float2 p0 = __half22float2(*(const __half2*)&accP[nt][0]);
            float2 q0 = __half22float2(*(const __half2*)&accQ[nt][0]);
            float2 p1 = __half22float2(*(const __half2*)&accP[nt][1]);
            float2 q1 = __half22float2(*(const __half2*)&accQ[nt][1]);
            float d0 = p0.x + q0.x + b2r[nt].x;   // row m0,   col n
            float d1 = p0.y + q0.y + b2r[nt].y;   // row m0,   col n+1
            float d2 = p1.x + q1.x + b2r[nt].x;   // row m0+8, col n
            float d3 = p1.y + q1.y + b2r[nt].y;   // row m0+8, col n+1
            sA0 = fmaf(fmaxf(d0, 0.f), wor[nt].x, sA0);
            sA0 = fmaf(fmaxf(d1, 0.f), wor[nt].y, sA0);
            sA1 = fmaf(fmaxf(d2, 0.f), wor[nt].x, sA1);
            sA1 = fmaf(fmaxf(d3, 0.f), wor[nt].y, sA1);
        }
        sA0 += __shfl_xor_sync(0xffffffffu, sA0, 1);
        sA0 += __shfl_xor_sync(0xffffffffu, sA0, 2);
        sA1 += __shfl_xor_sync(0xffffffffu, sA1, 1);
        sA1 += __shfl_xor_sync(0xffffffffu, sA1, 2);
        if (tid4 == 0) {
            g_T1[(size_t)i * NN + j0 + m0]     = sA0 + bo;
            g_T1[(size_t)i * NN + j0 + m0 + 8] = sA1 + bo;
        }
    }
}

// ---------------------------------------------------------------------------
// Kernel 3: logsumexp + diagonal + fused final reduction.
// ---------------------------------------------------------------------------
__global__ void lse_kernel(float* out) {
    __shared__ float sm[8], ss[8];
    const int tid = threadIdx.x;
    const int lane = tid & 31, wid = tid >> 5;
    double local = 0.0;

#pragma unroll 1
    for (int r = 0; r < 8; ++r) {
        const int i = blockIdx.x * 8 + r;
        const float4 v = ((const float4*)(g_T1 + (size_t)i * NN))[tid];

        float m = fmaxf(fmaxf(v.x, v.y), fmaxf(v.z, v.w));
#pragma unroll
        for (int o = 16; o > 0; o >>= 1)
            m = fmaxf(m, __shfl_xor_sync(0xffffffffu, m, o));
        if (lane == 0) sm[wid] = m;
        __syncthreads();
        float bm = sm[0];
#pragma unroll
        for (int w = 1; w < 8; ++w) bm = fmaxf(bm, sm[w]);

        float s = __expf(v.x - bm) + __expf(v.y - bm) +
                  __expf(v.z - bm) + __expf(v.w - bm);
#pragma unroll
        for (int o = 16; o > 0; o >>= 1)
            s += __shfl_xor_sync(0xffffffffu, s, o);
        if (lane == 0) ss[wid] = s;
        __syncthreads();

        if (tid == 0) {
            float tot = ss[0] + ss[1] + ss[2] + ss[3] +
                        ss[4] + ss[5] + ss[6] + ss[7];
            local += (double)g_T1[(size_t)i * NN + i]
                   - ((double)bm + log((double)tot));
        }
        __syncthreads();
    }

    if (tid == 0) {
        atomicAdd(&g_acc, local);
        __threadfence();
        if (atomicAdd(&g_cnt, 1) == 127) {
            double acc = atomicAdd(&g_acc, 0.0);
            out[0] = (float)(acc / NN + log((double)NN));
        }
    }
}

// ---------------------------------------------------------------------------
extern "C" void kernel_launch(void* const* d_in, const int* in_sizes, int n_in,
                              void* d_out, int out_size) {
    const float* z_c = (const float*)d_in[0];
    const float* z_d = (const float*)d_in[1];
    const float* W1  = (const float*)d_in[2];
    const float* b1  = (const float*)d_in[3];
    const float* W2  = (const float*)d_in[4];
    const float* b2  = (const float*)d_in[5];
    const float* Wo  = (const float*)d_in[6];
    const float* bo  = (const float*)d_in[7];
    float* out = (float*)d_out;

    prep_kernel<<<dim3(NN / 4, 2), 256>>>(z_c, z_d, W1, b1);
    pair_mma_kernel<<<16 * JSTRIDE, 128>>>(W2, b2, Wo, bo);
    lse_kernel<<<128, 256>>>(out);
}